// round 2
// baseline (speedup 1.0000x reference)
#include <cuda_runtime.h>
#include <cuda_bf16.h>
#include <math.h>

#define GX 128
#define GY 128
#define GZ 128
#define VDIM 28
#define NUM_RAYS 8192
#define NUM_SAMPLES 128
#define NVOX (GX*GY*GZ)

// Reduced grid: per voxel (sigma, r, g, b) after contracting SH coeffs with the
// (launch-constant) viewing-angle basis. 128^3 * 16B = 32 MB -> fits in L2.
__device__ float4 g_reduced[NVOX];

// ---------------------------------------------------------------------------
// Kernel 1: contract 28-dim features -> 4 floats per voxel.
// Pure streaming: 235 MB read, 32 MB write.
// ---------------------------------------------------------------------------
__global__ __launch_bounds__(256) void reduce_kernel(
    const float* __restrict__ grid, const float* __restrict__ ang)
{
    int v = blockIdx.x * blockDim.x + threadIdx.x;
    if (v >= NVOX) return;

    // SH degree-2 basis (constant per launch; recomputed per thread, cheap MUFU)
    float theta = ang[0], phi = ang[1];
    float st, ct, sp, cp;
    __sincosf(theta, &st, &ct);
    __sincosf(phi, &sp, &cp);
    const float y00 = 0.28209479177387814f;
    const float h3  = 0.4886025119029199f;
    const float q5  = 0.31539156525252005f;
    const float h15 = 1.0925484305920792f;
    const float q15 = 0.5462742152960396f;
    float b[9];
    b[0] = y00;
    b[1] = h3 * st * sp;
    b[2] = h3 * ct;
    b[3] = h3 * st * cp;
    b[4] = h15 * st * cp * st * sp;
    b[5] = h15 * st * sp * ct;
    b[6] = q5 * (3.0f * ct * ct - 1.0f);
    b[7] = h15 * st * cp * ct;
    b[8] = q15 * ((st * cp) * (st * cp) - (st * sp) * (st * sp));

    // 28 floats per voxel = 7 aligned float4 loads (stride 112 B, 16B aligned)
    const float4* vp = (const float4*)(grid + (size_t)v * VDIM);
    float f[VDIM];
    #pragma unroll
    for (int i = 0; i < 7; i++) {
        float4 t = vp[i];
        f[i*4+0] = t.x; f[i*4+1] = t.y; f[i*4+2] = t.z; f[i*4+3] = t.w;
    }

    float r = 0.f, g = 0.f, bl = 0.f;
    #pragma unroll
    for (int k = 0; k < 9; k++) {
        r  = fmaf(f[1  + k], b[k], r);
        g  = fmaf(f[10 + k], b[k], g);
        bl = fmaf(f[19 + k], b[k], bl);
    }
    g_reduced[v] = make_float4(f[0], r, g, bl);
}

// ---------------------------------------------------------------------------
// Kernel 2: per-ray rendering from reduced grid.
// One warp per ray; each lane owns 4 contiguous samples.
// ---------------------------------------------------------------------------
__device__ __forceinline__ float4 f4lerp(float4 a, float4 b, float t) {
    return make_float4(fmaf(b.x - a.x, t, a.x),
                       fmaf(b.y - a.y, t, a.y),
                       fmaf(b.z - a.z, t, a.z),
                       fmaf(b.w - a.w, t, a.w));
}

__device__ __forceinline__ float4 trilerp(float x, float y, float z) {
    int xi = (int)x, yi = (int)y, zi = (int)z;  // positions >= 0
    float xd = x - (float)xi, yd = y - (float)yi, zd = z - (float)zi;
    int i000 = (xi << 14) + (yi << 7) + zi;
    const float4* __restrict__ G = g_reduced;
    float4 c000 = G[i000];
    float4 c001 = G[i000 + 1];
    float4 c010 = G[i000 + GZ];
    float4 c011 = G[i000 + GZ + 1];
    float4 c100 = G[i000 + GY*GZ];
    float4 c101 = G[i000 + GY*GZ + 1];
    float4 c110 = G[i000 + GY*GZ + GZ];
    float4 c111 = G[i000 + GY*GZ + GZ + 1];
    float4 c00 = f4lerp(c000, c100, xd);
    float4 c01 = f4lerp(c001, c101, xd);
    float4 c10 = f4lerp(c010, c110, xd);
    float4 c11 = f4lerp(c011, c111, xd);
    float4 c0 = f4lerp(c00, c10, yd);
    float4 c1 = f4lerp(c01, c11, yd);
    return f4lerp(c0, c1, zd);
}

__global__ __launch_bounds__(256) void render_kernel(
    const float* __restrict__ pos, const float* __restrict__ dist,
    float* __restrict__ out)
{
    int gwarp = (blockIdx.x * blockDim.x + threadIdx.x) >> 5;
    int lane = threadIdx.x & 31;
    if (gwarp >= NUM_RAYS) return;

    // Samples s = lane*4 + j (j=0..3). Positions: 12 contiguous floats per lane,
    // 48B-aligned -> 3 float4 loads.
    const float4* p4 = (const float4*)(pos + (size_t)gwarp * NUM_SAMPLES * 3) + lane * 3;
    float4 a = p4[0], b = p4[1], c = p4[2];
    float px[4] = {a.x, a.w, b.z, c.y};
    float py[4] = {a.y, b.x, b.w, c.z};
    float pz[4] = {a.z, b.y, c.x, c.w};

    float4 d4 = ((const float4*)(dist + (size_t)gwarp * NUM_SAMPLES))[lane];
    float dd[4] = {d4.x, d4.y, d4.z, d4.w};

    float att[4];
    float rr[4], gg[4], bb[4];
    #pragma unroll
    for (int j = 0; j < 4; j++) {
        float4 s = trilerp(px[j], py[j], pz[j]);
        att[j] = expf(-s.x * dd[j]);
        rr[j] = s.y; gg[j] = s.z; bb[j] = s.w;
    }

    // Inclusive cumsum of att over the 128 samples of this ray.
    float p0 = att[0];
    float p1 = p0 + att[1];
    float p2 = p1 + att[2];
    float p3 = p2 + att[3];
    float tot = p3;
    #pragma unroll
    for (int o = 1; o < 32; o <<= 1) {
        float n = __shfl_up_sync(0xffffffffu, tot, o);
        if (lane >= o) tot += n;
    }
    float excl = tot - p3;  // sum of all samples before this lane's 4
    float T[4] = {excl + p0, excl + p1, excl + p2, excl + p3};

    float ar = 0.f, ag = 0.f, ab = 0.f;
    #pragma unroll
    for (int j = 0; j < 4; j++) {
        float w = T[j] * (1.0f - att[j]);
        ar = fmaf(w, rr[j], ar);
        ag = fmaf(w, gg[j], ag);
        ab = fmaf(w, bb[j], ab);
    }

    // Warp reduction
    #pragma unroll
    for (int o = 16; o > 0; o >>= 1) {
        ar += __shfl_xor_sync(0xffffffffu, ar, o);
        ag += __shfl_xor_sync(0xffffffffu, ag, o);
        ab += __shfl_xor_sync(0xffffffffu, ab, o);
    }
    if (lane == 0) {
        out[gwarp * 3 + 0] = ar;
        out[gwarp * 3 + 1] = ag;
        out[gwarp * 3 + 2] = ab;
    }
}

extern "C" void kernel_launch(void* const* d_in, const int* in_sizes, int n_in,
                              void* d_out, int out_size) {
    const float* voxel_grid = (const float*)d_in[0];
    const float* sample_positions = (const float*)d_in[1];
    const float* sample_distances = (const float*)d_in[2];
    const float* viewing_angle = (const float*)d_in[3];
    float* out = (float*)d_out;

    reduce_kernel<<<(NVOX + 255) / 256, 256>>>(voxel_grid, viewing_angle);
    // 8 warps/block -> 8 rays/block
    render_kernel<<<NUM_RAYS / 8, 256>>>(sample_positions, sample_distances, out);
}

// round 3
// speedup vs baseline: 1.0346x; 1.0346x over previous
#include <cuda_runtime.h>
#include <cuda_fp16.h>
#include <math.h>

#define GX 128
#define GY 128
#define GZ 128
#define VDIM 28
#define NUM_RAYS 8192
#define NUM_SAMPLES 128
#define NVOX (GX*GY*GZ)

// Paired reduced grid: entry v holds fp16 (sigma,r,g,b) for voxel v AND voxel v+1
// (its +z neighbor). 16 B per entry, always 16B-aligned -> one uint4 load gives
// both z-corners of a trilerp. 32 MB total, L2-resident.
__device__ uint4 g_pairs[NVOX];

// ---------------------------------------------------------------------------
// SH basis (degree 2), matching reference coefficient order.
// ---------------------------------------------------------------------------
__device__ __forceinline__ void sh_basis9(const float* __restrict__ ang, float* b) {
    float theta = ang[0], phi = ang[1];
    float st, ct, sp, cp;
    __sincosf(theta, &st, &ct);
    __sincosf(phi, &sp, &cp);
    const float y00 = 0.28209479177387814f;
    const float h3  = 0.4886025119029199f;
    const float q5  = 0.31539156525252005f;
    const float h15 = 1.0925484305920792f;
    const float q15 = 0.5462742152960396f;
    b[0] = y00;
    b[1] = h3 * st * sp;
    b[2] = h3 * ct;
    b[3] = h3 * st * cp;
    b[4] = h15 * st * cp * st * sp;
    b[5] = h15 * st * sp * ct;
    b[6] = q5 * (3.0f * ct * ct - 1.0f);
    b[7] = h15 * st * cp * ct;
    b[8] = q15 * ((st * cp) * (st * cp) - (st * sp) * (st * sp));
}

// Contract 28 features of voxel v -> packed fp16 (sigma, r | g, b) in a uint2.
__device__ __forceinline__ uint2 contract_voxel(const float* __restrict__ grid,
                                                const float* __restrict__ b, int v) {
    const float4* vp = (const float4*)(grid + (size_t)v * VDIM);
    float f[VDIM];
    #pragma unroll
    for (int i = 0; i < 7; i++) {
        float4 t = vp[i];
        f[i*4+0] = t.x; f[i*4+1] = t.y; f[i*4+2] = t.z; f[i*4+3] = t.w;
    }
    float r = 0.f, g = 0.f, bl = 0.f;
    #pragma unroll
    for (int k = 0; k < 9; k++) {
        r  = fmaf(f[1  + k], b[k], r);
        g  = fmaf(f[10 + k], b[k], g);
        bl = fmaf(f[19 + k], b[k], bl);
    }
    __half2 h0 = __floats2half2_rn(f[0], r);
    __half2 h1 = __floats2half2_rn(g, bl);
    uint2 u;
    u.x = *(const unsigned int*)&h0;
    u.y = *(const unsigned int*)&h1;
    return u;
}

// ---------------------------------------------------------------------------
// Kernel 1: contract 28-dim features -> fp16x4, pack with +z neighbor.
// Streaming: 235 MB read, 32 MB write. smem tile supplies the neighbor.
// ---------------------------------------------------------------------------
__global__ __launch_bounds__(256) void reduce_kernel(
    const float* __restrict__ grid, const float* __restrict__ ang)
{
    __shared__ uint2 s[257];
    float b[9];
    sh_basis9(ang, b);

    int base = blockIdx.x * 256;
    int t = threadIdx.x;
    int v = base + t;
    s[t] = contract_voxel(grid, b, v);
    if (t == 0) {
        int v2 = base + 256;
        if (v2 >= NVOX) v2 = NVOX - 1;   // value never read; keep in-bounds
        s[256] = contract_voxel(grid, b, v2);
    }
    __syncthreads();
    uint2 a = s[t], c = s[t + 1];
    g_pairs[v] = make_uint4(a.x, a.y, c.x, c.y);
}

// ---------------------------------------------------------------------------
// Kernel 2: per-ray rendering. One warp per ray, 4 samples per lane.
// Trilerp = 4 aligned uint4 gathers (each load covers the z / z+1 corner pair).
// ---------------------------------------------------------------------------
__device__ __forceinline__ float4 zlerp_pair(uint4 t, float zd) {
    // t = {sigma0,r0 | g0,b0 | sigma1,r1 | g1,b1} as 4x half2
    float2 a0 = __half22float2(*(__half2*)&t.x);
    float2 a1 = __half22float2(*(__half2*)&t.y);
    float2 b0 = __half22float2(*(__half2*)&t.z);
    float2 b1 = __half22float2(*(__half2*)&t.w);
    return make_float4(fmaf(b0.x - a0.x, zd, a0.x),
                       fmaf(b0.y - a0.y, zd, a0.y),
                       fmaf(b1.x - a1.x, zd, a1.x),
                       fmaf(b1.y - a1.y, zd, a1.y));
}

__device__ __forceinline__ float4 f4lerp(float4 a, float4 b, float t) {
    return make_float4(fmaf(b.x - a.x, t, a.x),
                       fmaf(b.y - a.y, t, a.y),
                       fmaf(b.z - a.z, t, a.z),
                       fmaf(b.w - a.w, t, a.w));
}

__device__ __forceinline__ float4 trilerp(float x, float y, float z) {
    int xi = (int)x, yi = (int)y, zi = (int)z;  // positions in [0, 126]
    float xd = x - (float)xi, yd = y - (float)yi, zd = z - (float)zi;
    int i = (xi << 14) + (yi << 7) + zi;
    const uint4* __restrict__ G = g_pairs;
    float4 v00 = zlerp_pair(G[i],                zd);  // (x0,y0)
    float4 v01 = zlerp_pair(G[i + GZ],           zd);  // (x0,y1)
    float4 v10 = zlerp_pair(G[i + GY*GZ],        zd);  // (x1,y0)
    float4 v11 = zlerp_pair(G[i + GY*GZ + GZ],   zd);  // (x1,y1)
    float4 v0 = f4lerp(v00, v10, xd);
    float4 v1 = f4lerp(v01, v11, xd);
    return f4lerp(v0, v1, yd);
}

__global__ __launch_bounds__(256) void render_kernel(
    const float* __restrict__ pos, const float* __restrict__ dist,
    float* __restrict__ out)
{
    int gwarp = (blockIdx.x * blockDim.x + threadIdx.x) >> 5;
    int lane = threadIdx.x & 31;
    if (gwarp >= NUM_RAYS) return;

    // 12 contiguous floats of positions per lane -> 3 aligned float4 loads.
    const float4* p4 = (const float4*)(pos + (size_t)gwarp * NUM_SAMPLES * 3) + lane * 3;
    float4 a = p4[0], b = p4[1], c = p4[2];
    float px[4] = {a.x, a.w, b.z, c.y};
    float py[4] = {a.y, b.x, b.w, c.z};
    float pz[4] = {a.z, b.y, c.x, c.w};

    float4 d4 = ((const float4*)(dist + (size_t)gwarp * NUM_SAMPLES))[lane];
    float dd[4] = {d4.x, d4.y, d4.z, d4.w};

    float att[4], rr[4], gg[4], bb[4];
    #pragma unroll
    for (int j = 0; j < 4; j++) {
        float4 s = trilerp(px[j], py[j], pz[j]);
        att[j] = expf(-s.x * dd[j]);
        rr[j] = s.y; gg[j] = s.z; bb[j] = s.w;
    }

    // Inclusive cumsum of att across the ray (4-wide serial + warp scan).
    float p0 = att[0];
    float p1 = p0 + att[1];
    float p2 = p1 + att[2];
    float p3 = p2 + att[3];
    float tot = p3;
    #pragma unroll
    for (int o = 1; o < 32; o <<= 1) {
        float n = __shfl_up_sync(0xffffffffu, tot, o);
        if (lane >= o) tot += n;
    }
    float excl = tot - p3;
    float T[4] = {excl + p0, excl + p1, excl + p2, excl + p3};

    float ar = 0.f, ag = 0.f, ab = 0.f;
    #pragma unroll
    for (int j = 0; j < 4; j++) {
        float w = T[j] * (1.0f - att[j]);
        ar = fmaf(w, rr[j], ar);
        ag = fmaf(w, gg[j], ag);
        ab = fmaf(w, bb[j], ab);
    }

    #pragma unroll
    for (int o = 16; o > 0; o >>= 1) {
        ar += __shfl_xor_sync(0xffffffffu, ar, o);
        ag += __shfl_xor_sync(0xffffffffu, ag, o);
        ab += __shfl_xor_sync(0xffffffffu, ab, o);
    }
    if (lane == 0) {
        out[gwarp * 3 + 0] = ar;
        out[gwarp * 3 + 1] = ag;
        out[gwarp * 3 + 2] = ab;
    }
}

extern "C" void kernel_launch(void* const* d_in, const int* in_sizes, int n_in,
                              void* d_out, int out_size) {
    const float* voxel_grid = (const float*)d_in[0];
    const float* sample_positions = (const float*)d_in[1];
    const float* sample_distances = (const float*)d_in[2];
    const float* viewing_angle = (const float*)d_in[3];
    float* out = (float*)d_out;

    reduce_kernel<<<NVOX / 256, 256>>>(voxel_grid, viewing_angle);
    render_kernel<<<NUM_RAYS / 8, 256>>>(sample_positions, sample_distances, out);
}

// round 4
// speedup vs baseline: 1.1906x; 1.1508x over previous
#include <cuda_runtime.h>
#include <cuda_fp16.h>
#include <math.h>

#define GX 128
#define GY 128
#define GZ 128
#define VDIM 28
#define NUM_RAYS 8192
#define NUM_SAMPLES 128
#define NVOX (GX*GY*GZ)

// Paired reduced grid: entry v holds fp16 (sigma,r,g,b) for voxel v AND voxel v+1
// (its +z neighbor). One aligned 16B load gives both z-corners of a trilerp.
// 32 MB total -> L2-resident.
__device__ uint4 g_pairs[NVOX];

// ---------------------------------------------------------------------------
// SH basis (degree 2), reference coefficient order.
// ---------------------------------------------------------------------------
__device__ __forceinline__ void sh_basis9(const float* __restrict__ ang, float* b) {
    float theta = ang[0], phi = ang[1];
    float st, ct, sp, cp;
    __sincosf(theta, &st, &ct);
    __sincosf(phi, &sp, &cp);
    const float y00 = 0.28209479177387814f;
    const float h3  = 0.4886025119029199f;
    const float q5  = 0.31539156525252005f;
    const float h15 = 1.0925484305920792f;
    const float q15 = 0.5462742152960396f;
    b[0] = y00;
    b[1] = h3 * st * sp;
    b[2] = h3 * ct;
    b[3] = h3 * st * cp;
    b[4] = h15 * st * cp * st * sp;
    b[5] = h15 * st * sp * ct;
    b[6] = q5 * (3.0f * ct * ct - 1.0f);
    b[7] = h15 * st * cp * ct;
    b[8] = q15 * ((st * cp) * (st * cp) - (st * sp) * (st * sp));
}

// Contract 28 features of voxel v -> packed fp16 (sigma,r | g,b).
// Raw grid reads use __ldcs (evict-first) so the 235 MB stream doesn't evict
// the freshly written g_pairs from L2 before render consumes it.
__device__ __forceinline__ uint2 contract_voxel(const float* __restrict__ grid,
                                                const float* __restrict__ b, int v) {
    const float4* vp = (const float4*)(grid + (size_t)v * VDIM);
    float f[VDIM];
    #pragma unroll
    for (int i = 0; i < 7; i++) {
        float4 t = __ldcs(vp + i);
        f[i*4+0] = t.x; f[i*4+1] = t.y; f[i*4+2] = t.z; f[i*4+3] = t.w;
    }
    float r = 0.f, g = 0.f, bl = 0.f;
    #pragma unroll
    for (int k = 0; k < 9; k++) {
        r  = fmaf(f[1  + k], b[k], r);
        g  = fmaf(f[10 + k], b[k], g);
        bl = fmaf(f[19 + k], b[k], bl);
    }
    __half2 h0 = __floats2half2_rn(f[0], r);
    __half2 h1 = __floats2half2_rn(g, bl);
    uint2 u;
    u.x = *(const unsigned int*)&h0;
    u.y = *(const unsigned int*)&h1;
    return u;
}

// ---------------------------------------------------------------------------
// Kernel 1: contract + pack with +z neighbor (smem supplies the neighbor).
// ---------------------------------------------------------------------------
__global__ __launch_bounds__(256) void reduce_kernel(
    const float* __restrict__ grid, const float* __restrict__ ang)
{
    __shared__ uint2 s[257];
    float b[9];
    sh_basis9(ang, b);

    int base = blockIdx.x * 256;
    int t = threadIdx.x;
    int v = base + t;
    s[t] = contract_voxel(grid, b, v);
    if (t == 0) {
        int v2 = base + 256;
        if (v2 >= NVOX) v2 = NVOX - 1;   // value never read; keep in-bounds
        s[256] = contract_voxel(grid, b, v2);
    }
    __syncthreads();
    uint2 a = s[t], c = s[t + 1];
    g_pairs[v] = make_uint4(a.x, a.y, c.x, c.y);
}

// ---------------------------------------------------------------------------
// Kernel 2: rendering, ONE SAMPLE PER THREAD (max MLP against random gathers).
// 128 threads (4 warps) per ray, 2 rays per 256-thread block.
// ---------------------------------------------------------------------------
__device__ __forceinline__ float4 zlerp_pair(uint4 t, float zd) {
    float2 a0 = __half22float2(*(__half2*)&t.x);
    float2 a1 = __half22float2(*(__half2*)&t.y);
    float2 b0 = __half22float2(*(__half2*)&t.z);
    float2 b1 = __half22float2(*(__half2*)&t.w);
    return make_float4(fmaf(b0.x - a0.x, zd, a0.x),
                       fmaf(b0.y - a0.y, zd, a0.y),
                       fmaf(b1.x - a1.x, zd, a1.x),
                       fmaf(b1.y - a1.y, zd, a1.y));
}

__device__ __forceinline__ float4 f4lerp(float4 a, float4 b, float t) {
    return make_float4(fmaf(b.x - a.x, t, a.x),
                       fmaf(b.y - a.y, t, a.y),
                       fmaf(b.z - a.z, t, a.z),
                       fmaf(b.w - a.w, t, a.w));
}

__device__ __forceinline__ float4 trilerp(float x, float y, float z) {
    int xi = (int)x, yi = (int)y, zi = (int)z;   // positions in [0, 126]
    float xd = x - (float)xi, yd = y - (float)yi, zd = z - (float)zi;
    int i = (xi << 14) + (yi << 7) + zi;
    const uint4* __restrict__ G = g_pairs;
    uint4 t00 = G[i];
    uint4 t01 = G[i + GZ];
    uint4 t10 = G[i + GY*GZ];
    uint4 t11 = G[i + GY*GZ + GZ];
    float4 v00 = zlerp_pair(t00, zd);
    float4 v01 = zlerp_pair(t01, zd);
    float4 v10 = zlerp_pair(t10, zd);
    float4 v11 = zlerp_pair(t11, zd);
    float4 v0 = f4lerp(v00, v10, xd);
    float4 v1 = f4lerp(v01, v11, xd);
    return f4lerp(v0, v1, yd);
}

__global__ __launch_bounds__(256) void render_kernel(
    const float* __restrict__ pos, const float* __restrict__ dist,
    float* __restrict__ out)
{
    __shared__ float s_wsum[8];      // per-warp att totals
    __shared__ float s_acc[8][3];    // per-warp rgb partials

    int tid  = threadIdx.x;
    int wid  = tid >> 5;             // warp in block: 0..7
    int lane = tid & 31;
    int wir  = wid & 3;              // warp within ray: 0..3
    int rbase = wid & 4;             // first warp index of this thread's ray
    int ray  = blockIdx.x * 2 + (tid >> 7);
    int s    = tid & 127;            // sample index within ray

    // Per-thread sample position (3 scalar loads) + distance.
    const float* p = pos + (size_t)ray * (NUM_SAMPLES * 3) + s * 3;
    float px = p[0], py = p[1], pz = p[2];
    float d  = dist[(size_t)ray * NUM_SAMPLES + s];

    float4 sm = trilerp(px, py, pz);
    float att = __expf(-sm.x * d);

    // Inclusive scan of att over the ray's 128 samples:
    // warp inclusive scan, then add preceding warps' totals via smem.
    float inc = att;
    #pragma unroll
    for (int o = 1; o < 32; o <<= 1) {
        float n = __shfl_up_sync(0xffffffffu, inc, o);
        if (lane >= o) inc += n;
    }
    if (lane == 31) s_wsum[wid] = inc;
    __syncthreads();
    float off = 0.f;
    #pragma unroll
    for (int w = 0; w < 3; w++)
        if (w < wir) off += s_wsum[rbase + w];
    float T = inc + off;

    float w = T * (1.0f - att);
    float ar = w * sm.y, ag = w * sm.z, ab = w * sm.w;

    // Warp reduction, then combine the ray's 4 warps.
    #pragma unroll
    for (int o = 16; o > 0; o >>= 1) {
        ar += __shfl_xor_sync(0xffffffffu, ar, o);
        ag += __shfl_xor_sync(0xffffffffu, ag, o);
        ab += __shfl_xor_sync(0xffffffffu, ab, o);
    }
    if (lane == 0) {
        s_acc[wid][0] = ar;
        s_acc[wid][1] = ag;
        s_acc[wid][2] = ab;
    }
    __syncthreads();
    if (wir == 0 && lane < 3) {
        float v = s_acc[rbase + 0][lane] + s_acc[rbase + 1][lane]
                + s_acc[rbase + 2][lane] + s_acc[rbase + 3][lane];
        out[ray * 3 + lane] = v;
    }
}

extern "C" void kernel_launch(void* const* d_in, const int* in_sizes, int n_in,
                              void* d_out, int out_size) {
    const float* voxel_grid = (const float*)d_in[0];
    const float* sample_positions = (const float*)d_in[1];
    const float* sample_distances = (const float*)d_in[2];
    const float* viewing_angle = (const float*)d_in[3];
    float* out = (float*)d_out;

    reduce_kernel<<<NVOX / 256, 256>>>(voxel_grid, viewing_angle);
    render_kernel<<<NUM_RAYS / 2, 256>>>(sample_positions, sample_distances, out);
}